// round 11
// baseline (speedup 1.0000x reference)
#include <cuda_runtime.h>
#include <math.h>

// ---------------------------------------------------------------------------
// Problem constants
//   x:  (2, 64, 192, 192)
//   out:(2, 64, 384, 384) fp32
// ---------------------------------------------------------------------------
#define B_   2
#define C_   64
#define H1_  192
#define W1_  192
#define H2_  384
#define W2_  384

// ---------------------------------------------------------------------------
// f32x2 packed-FMA helpers (sm_103a FFMA2 — only reachable via PTX)
// ---------------------------------------------------------------------------
__device__ __forceinline__ unsigned long long pack2(float v) {
    unsigned long long r;
    asm("mov.b64 %0, {%1, %1};" : "=l"(r) : "f"(v));
    return r;
}
__device__ __forceinline__ void fma2(unsigned long long& d,
                                     unsigned long long a,
                                     unsigned long long b) {
    asm("fma.rn.f32x2 %0, %1, %2, %0;" : "+l"(d) : "l"(a), "l"(b));
}
__device__ __forceinline__ float2 unpack2(unsigned long long v) {
    float2 f;
    asm("mov.b64 {%0, %1}, %2;" : "=f"(f.x), "=f"(f.y) : "l"(v));
    return f;
}

// ---------------------------------------------------------------------------
// Scratch (static device globals; no cudaMalloc allowed)
// ---------------------------------------------------------------------------
__device__ float g_off1[B_ * 27 * H1_ * W1_];   // offsets stage 1
__device__ float g_h1  [B_ * C_ * H1_ * W1_];   // elu(dcn1)
__device__ float g_h1up[B_ * C_ * H2_ * W2_];   // upsample2x(h1), NCHW
__device__ float g_off2[B_ * 27 * H2_ * W2_];   // offsets stage 2
__device__ float g_r   [B_ * C_ * H1_ * W1_];   // 1x1 residual conv
__device__ float g_w1t [9 * 64 * 64];           // dcn1 weights (k,c,o)
__device__ float g_w2t [9 * 64 * 64];           // dcn2 weights (k,c,o)
__device__ float g_ow1t[64 * 9 * 32];           // offset conv1 weights (c,k,o-pad32)
__device__ float g_ow2t[64 * 9 * 32];           // offset conv2 weights (c,k,o-pad32)
__device__ float g_xt   [B_ * H1_ * W1_ * 64];  // x, NHWC (gather source dcn1)
__device__ float g_h1upt[B_ * H2_ * W2_ * 64];  // h1up, NHWC (gather source dcn2)

// ---------------------------------------------------------------------------
// Merged weight transposes (one launch)
// ---------------------------------------------------------------------------
__global__ void transpose_all_kernel(const float* __restrict__ w1,
                                     const float* __restrict__ w2,
                                     const float* __restrict__ ow1,
                                     const float* __restrict__ ow2) {
    int i = blockIdx.x * 256 + threadIdx.x;
    if (i < 2 * 36864) {
        const float* w = (i < 36864) ? w1 : w2;
        float* wt = (i < 36864) ? g_w1t : g_w2t;
        int j = (i < 36864) ? i : i - 36864;
        int o = j & 63;
        int c = (j >> 6) & 63;
        int k = j >> 12;
        wt[j] = w[(o * 64 + c) * 9 + k];
    } else {
        int j = i - 2 * 36864;
        if (j >= 2 * 18432) return;
        const float* w = (j < 18432) ? ow1 : ow2;
        float* wt = (j < 18432) ? g_ow1t : g_ow2t;
        int jj = (j < 18432) ? j : j - 18432;
        int c = jj / 288;
        int r = jj - c * 288;
        int k = r >> 5;
        int o = r & 31;
        wt[jj] = (o < 27) ? w[(o * 64 + c) * 9 + k] : 0.0f;
    }
}

// ---------------------------------------------------------------------------
// NCHW -> NHWC transpose (64 channels). Block = 256 thr, 64 pixels x 64 ch.
// Reads coalesced per channel; writes coalesced per pixel; smem 64x65 tile.
// ---------------------------------------------------------------------------
__global__ void __launch_bounds__(256) nchw_to_nhwc_kernel(
    const float* __restrict__ in, float* __restrict__ out, int HW)
{
    __shared__ float t[64][65];
    const int pix0 = blockIdx.x * 64;
    const int b = blockIdx.y;
    const float* inb = in + (size_t)b * 64 * HW;
    float* outb = out + (size_t)b * HW * 64;
    const int tid = threadIdx.x;
#pragma unroll
    for (int it = 0; it < 16; it++) {
        int idx = it * 256 + tid;
        int c = idx >> 6, p = idx & 63;
        t[c][p] = __ldg(inb + (size_t)c * HW + pix0 + p);
    }
    __syncthreads();
#pragma unroll
    for (int it = 0; it < 16; it++) {
        int idx = it * 256 + tid;
        int p = idx >> 6, c = idx & 63;
        outb[(size_t)(pix0 + p) * 64 + c] = t[c][p];
    }
}

// ---------------------------------------------------------------------------
// 3x3 conv, Cin=64, Cout=27 (28 acc = 14 f32x2), pad=1, NCHW
// block: 256 threads = 16x32 output tile (2 rows per thread: ty, ty+16)
// DOUBLE-BUFFERED (R9 measured win): one sync per channel.
// ---------------------------------------------------------------------------
__global__ void __launch_bounds__(256) conv3x3_27_kernel(
    const float* __restrict__ in,    // (B,64,H,W)
    const float* __restrict__ wt,    // (64,9,32) transposed+padded
    const float* __restrict__ bias,  // (27)
    float* __restrict__ out,         // (B,27,H,W)
    int H, int W)
{
    __shared__ __align__(16) float tile[2][34][18];   // 2 x (32 rows + halo)
    __shared__ __align__(16) float wsm[2][288];

    const int tid = threadIdx.x;
    const int tx = tid & 15;
    const int ty = tid >> 4;          // 0..15 -> rows ty and ty+16
    const int bx = blockIdx.x * 16;
    const int by = blockIdx.y * 32;
    const int b  = blockIdx.z;

    // hoisted halo-load coordinates: 34*18 = 612 values, 3 slots
    int gofs[3];
    bool gval[3];
    bool ghave[3];
#pragma unroll
    for (int s = 0; s < 3; s++) {
        int idx = tid + s * 256;
        ghave[s] = (idx < 612);
        int iy = idx / 18, ix = idx - iy * 18;
        int yy = by + iy - 1, xx = bx + ix - 1;
        gval[s] = ghave[s] && (yy >= 0 && yy < H && xx >= 0 && xx < W);
        gofs[s] = yy * W + xx;
    }
    const bool haveW1 = (tid < 32);   // weights slot1 = tid+256 < 288

    unsigned long long acc2a[14], acc2b[14];
#pragma unroll
    for (int j = 0; j < 14; j++) { acc2a[j] = 0ULL; acc2b[j] = 0ULL; }

    const float* pc = in + (size_t)b * 64 * H * W;
    const float* pw = wt;
    const int HW = H * W;

    // stage channel 0 into buffer 0
#pragma unroll
    for (int s = 0; s < 3; s++)
        if (ghave[s])
            ((float*)tile[0])[tid + s * 256] = gval[s] ? __ldg(pc + gofs[s]) : 0.0f;
    wsm[0][tid] = __ldg(pw + tid);
    if (haveW1) wsm[0][tid + 256] = __ldg(pw + tid + 256);
    __syncthreads();

    for (int c = 0; c < 64; c++) {
        const int cur = c & 1;

        // prefetch next channel into registers (LDG only, overlaps compute)
        float nv[3];
        float nw0 = 0.0f, nw1 = 0.0f;
        if (c < 63) {
            const float* pn = pc + HW;
            const float* pwn = pw + 288;
#pragma unroll
            for (int s = 0; s < 3; s++)
                nv[s] = (ghave[s] && gval[s]) ? __ldg(pn + gofs[s]) : 0.0f;
            nw0 = __ldg(pwn + tid);
            if (haveW1) nw1 = __ldg(pwn + tid + 256);
        }

        // compute on current buffer
#pragma unroll
        for (int k = 0; k < 9; k++) {
            float xa = tile[cur][ty + k / 3][tx + k % 3];
            float xb = tile[cur][ty + 16 + k / 3][tx + k % 3];
            unsigned long long xa2 = pack2(xa);
            unsigned long long xb2 = pack2(xb);
            const ulonglong2* wr = (const ulonglong2*)(&wsm[cur][k * 32]);
#pragma unroll
            for (int g = 0; g < 7; g++) {
                ulonglong2 wv = wr[g];
                fma2(acc2a[2 * g + 0], xa2, wv.x);
                fma2(acc2a[2 * g + 1], xa2, wv.y);
                fma2(acc2b[2 * g + 0], xb2, wv.x);
                fma2(acc2b[2 * g + 1], xb2, wv.y);
            }
        }

        // store prefetched channel into alternate buffer
        if (c < 63) {
            const int nxt = cur ^ 1;
#pragma unroll
            for (int s = 0; s < 3; s++)
                if (ghave[s]) ((float*)tile[nxt])[tid + s * 256] = nv[s];
            wsm[nxt][tid] = nw0;
            if (haveW1) wsm[nxt][tid + 256] = nw1;
        }
        __syncthreads();
        pc += HW;
        pw += 288;
    }

    const int gya = by + ty;
    const int gyb = gya + 16;
    const int gx  = bx + tx;
    float fa[28], fb[28];
#pragma unroll
    for (int j = 0; j < 14; j++) {
        float2 t0 = unpack2(acc2a[j]);
        float2 t1 = unpack2(acc2b[j]);
        fa[2 * j] = t0.x; fa[2 * j + 1] = t0.y;
        fb[2 * j] = t1.x; fb[2 * j + 1] = t1.y;
    }
#pragma unroll
    for (int o = 0; o < 27; o++) {
        float bi = __ldg(bias + o);
        out[(((size_t)b * 27 + o) * H + gya) * W + gx] = fa[o] + bi;
        out[(((size_t)b * 27 + o) * H + gyb) * W + gx] = fb[o] + bi;
    }
}

// ---------------------------------------------------------------------------
// 1x1 conv, 64->64 (residual path), f32x2
// ---------------------------------------------------------------------------
__global__ void __launch_bounds__(256) conv1x1_kernel(
    const float* __restrict__ in,   // (B,64,HW)
    const float* __restrict__ w,    // (64,64) (o,c)
    const float* __restrict__ bias, // (64)
    float* __restrict__ out,        // (B,64,HW)
    int HW)
{
    __shared__ __align__(16) float ws[64 * 64];  // transposed: ws[c*64+o]
    const int tid = threadIdx.x;
    for (int i = tid; i < 4096; i += 256) {
        int c = i >> 6, o = i & 63;
        ws[i] = __ldg(w + o * 64 + c);
    }
    __syncthreads();

    const int b = blockIdx.y;
    const int p = blockIdx.x * 256 + tid;
    if (p >= HW) return;

    const float* inb = in + (size_t)b * 64 * HW + p;
    unsigned long long acc2[32];
#pragma unroll
    for (int j = 0; j < 32; j++) acc2[j] = 0ULL;

    for (int c = 0; c < 64; c++) {
        float xv = __ldg(inb + (size_t)c * HW);
        unsigned long long vv = pack2(xv);
        const ulonglong2* wr = (const ulonglong2*)(ws + c * 64);
#pragma unroll
        for (int g = 0; g < 16; g++) {
            ulonglong2 t = wr[g];
            fma2(acc2[2 * g + 0], vv, t.x);
            fma2(acc2[2 * g + 1], vv, t.y);
        }
    }
    float* ob = out + (size_t)b * 64 * HW + p;
#pragma unroll
    for (int j = 0; j < 32; j++) {
        float2 f = unpack2(acc2[j]);
        ob[(size_t)(2 * j + 0) * HW] = f.x + __ldg(bias + 2 * j + 0);
        ob[(size_t)(2 * j + 1) * HW] = f.y + __ldg(bias + 2 * j + 1);
    }
}

// ---------------------------------------------------------------------------
// bilinear 2x upsample, jax.image.resize semantics (NCHW -> NCHW)
// ---------------------------------------------------------------------------
__global__ void __launch_bounds__(256) upsample2x_kernel(
    const float* __restrict__ in, float* __restrict__ out, int BC, int H, int W)
{
    const int W2 = 2 * W, H2 = 2 * H;
    int idx = blockIdx.x * 256 + threadIdx.x;
    int total = BC * H2 * W2;
    if (idx >= total) return;
    int x = idx % W2;
    int t = idx / W2;
    int y = t % H2;
    int c = t / H2;
    float sy = y * 0.5f - 0.25f;
    float sx = x * 0.5f - 0.25f;
    float y0f = floorf(sy), x0f = floorf(sx);
    float wy = sy - y0f, wx = sx - x0f;
    int y0 = (int)y0f, x0 = (int)x0f;
    int yc0 = min(max(y0, 0), H - 1), yc1 = min(max(y0 + 1, 0), H - 1);
    int xc0 = min(max(x0, 0), W - 1), xc1 = min(max(x0 + 1, 0), W - 1);
    const float* p = in + (size_t)c * H * W;
    float v = (1.0f - wy) * ((1.0f - wx) * __ldg(p + yc0 * W + xc0) + wx * __ldg(p + yc0 * W + xc1))
            +         wy  * ((1.0f - wx) * __ldg(p + yc1 * W + xc0) + wx * __ldg(p + yc1 * W + xc1));
    out[idx] = v;
}

// ---------------------------------------------------------------------------
// DCNv2 + ELU (+ optional fused residual-upsample add for stage 2)
// R10 core with NHWC GATHER:
// Block = 128 threads = 4 warps. Tile = 128 pixels (TILEW cols x ROWS rows).
// Phase 1: warp w gathers its 16 channels for its 4 px/thread from the NHWC
//          image — 4 float4 loads per corner (channels contiguous!), packed
//          f32x2 sampling, scalar STS into s_s[c][px].
// Phase 2: warp w owns outputs [16w,16w+16) x 128 px, weights via LDS128.
// ---------------------------------------------------------------------------
template <int H, int W, int TILEW, int ROWS, bool RES>
__global__ void __launch_bounds__(128) dcn_kernel(
    const float* __restrict__ imgt,  // (B,H,W,64) NHWC gather source
    const float* __restrict__ off,   // (B,27,H,W)
    const float* __restrict__ wt,    // (9,64,64) (k,c,o)
    const float* __restrict__ bias,  // (64)
    const float* __restrict__ res,   // (B,64,H/2,W/2) or nullptr
    float* __restrict__ out)         // (B,64,H,W)
{
    static_assert(TILEW * ROWS == 128, "tile must be 128 px");
    __shared__ __align__(16) float s_s[64][128];  // [c][px]
    __shared__ __align__(16) float w_s[4096];     // one tap's 64x64 slab

    const int tid  = threadIdx.x;
    const int lane = tid & 31;
    const int warp = tid >> 5;          // 0..3
    const int cgrp = warp * 16;         // phase-1 channel group == phase-2 o group
    const int h0 = blockIdx.y * ROWS;
    const int bx = blockIdx.x * TILEW;
    const int b  = blockIdx.z;
    const int HW = H * W;
    const float* imgtb = imgt + (size_t)b * HW * 64;
    const float* offb  = off + (size_t)b * 27 * HW;

    // this thread's 4 pixels: px = lane + q*32
    int pwv[4], hv[4], pidx[4];
#pragma unroll
    for (int q = 0; q < 4; q++) {
        int px  = lane + q * 32;
        int row = px / TILEW;
        int col = px - row * TILEW;
        pwv[q] = bx + col;
        hv[q]  = h0 + row;
        pidx[q] = hv[q] * W + pwv[q];
    }

    unsigned long long acc[32];   // [o-pair j(8)][px q(4)] -> acc[j*4+q]
#pragma unroll
    for (int i = 0; i < 32; i++) acc[i] = 0ULL;

    for (int k = 0; k < 9; k++) {
        __syncthreads();  // protect s_s / w_s against previous iteration's readers
        // stage this tap's 64x64 weight slab (128 threads x 8 float4)
        {
            const float4* src = (const float4*)(wt + k * 4096);
            float4* dst = (float4*)w_s;
#pragma unroll
            for (int i = tid; i < 1024; i += 128) dst[i] = src[i];
        }

        // phase 1: per pixel — tap params, then NHWC float4 gather of the
        // warp's 16 channels with packed f32x2 sampling
#pragma unroll
        for (int q = 0; q < 4; q++) {
            const int px = lane + q * 32;

            float dy = __ldg(offb + (2 * k) * HW + pidx[q]);
            float dx = __ldg(offb + (2 * k + 1) * HW + pidx[q]);
            float mz = __ldg(offb + (18 + k) * HW + pidx[q]);
            float m  = 1.0f / (1.0f + expf(-mz));

            float yy = (float)(hv[q] - 1 + k / 3) + dy;
            float xx = (float)(pwv[q] - 1 + k % 3) + dx;
            float y0f = floorf(yy), x0f = floorf(xx);
            float wy = yy - y0f, wx = xx - x0f;
            int y0 = (int)y0f, x0 = (int)x0f;
            int y1 = y0 + 1,   x1 = x0 + 1;
            float fy0 = (y0 >= 0 && y0 < H) ? 1.0f : 0.0f;
            float fy1 = (y1 >= 0 && y1 < H) ? 1.0f : 0.0f;
            float fx0 = (x0 >= 0 && x0 < W) ? 1.0f : 0.0f;
            float fx1 = (x1 >= 0 && x1 < W) ? 1.0f : 0.0f;
            float w00 = (1.0f - wy) * (1.0f - wx) * fy0 * fx0 * m;
            float w01 = (1.0f - wy) * wx          * fy0 * fx1 * m;
            float w10 = wy          * (1.0f - wx) * fy1 * fx0 * m;
            float w11 = wy          * wx          * fy1 * fx1 * m;
            int yc0 = min(max(y0, 0), H - 1), yc1 = min(max(y1, 0), H - 1);
            int xc0 = min(max(x0, 0), W - 1), xc1 = min(max(x1, 0), W - 1);

            const float4* p00 = (const float4*)(imgtb + (size_t)(yc0 * W + xc0) * 64 + cgrp);
            const float4* p01 = (const float4*)(imgtb + (size_t)(yc0 * W + xc1) * 64 + cgrp);
            const float4* p10 = (const float4*)(imgtb + (size_t)(yc1 * W + xc0) * 64 + cgrp);
            const float4* p11 = (const float4*)(imgtb + (size_t)(yc1 * W + xc1) * 64 + cgrp);
            const unsigned long long W00 = pack2(w00), W01 = pack2(w01);
            const unsigned long long W10 = pack2(w10), W11 = pack2(w11);

#pragma unroll
            for (int g = 0; g < 4; g++) {
                float4 v00 = __ldg(p00 + g);
                float4 v01 = __ldg(p01 + g);
                float4 v10 = __ldg(p10 + g);
                float4 v11 = __ldg(p11 + g);
                ulonglong2 u00 = *(ulonglong2*)&v00;
                ulonglong2 u01 = *(ulonglong2*)&v01;
                ulonglong2 u10 = *(ulonglong2*)&v10;
                ulonglong2 u11 = *(ulonglong2*)&v11;
                unsigned long long r0 = 0ULL, r1 = 0ULL;
                fma2(r0, W00, u00.x); fma2(r0, W01, u01.x);
                fma2(r0, W10, u10.x); fma2(r0, W11, u11.x);
                fma2(r1, W00, u00.y); fma2(r1, W01, u01.y);
                fma2(r1, W10, u10.y); fma2(r1, W11, u11.y);
                float2 f0 = unpack2(r0), f1 = unpack2(r1);
                const int cb = cgrp + g * 4;
                s_s[cb + 0][px] = f0.x;
                s_s[cb + 1][px] = f0.y;
                s_s[cb + 2][px] = f1.x;
                s_s[cb + 3][px] = f1.y;
            }
        }
        __syncthreads();

        // phase 2: warp's 16 outputs x 128 pixels, 32 FFMA2 per c per thread
#pragma unroll 4
        for (int c = 0; c < 64; c++) {
            unsigned long long v[4];
#pragma unroll
            for (int q = 0; q < 4; q++) v[q] = pack2(s_s[c][lane + q * 32]);
            const ulonglong2* wr = (const ulonglong2*)(w_s + c * 64 + cgrp);
            ulonglong2 wp0 = wr[0], wp1 = wr[1], wp2 = wr[2], wp3 = wr[3];
#pragma unroll
            for (int q = 0; q < 4; q++) {
                fma2(acc[0 * 4 + q], v[q], wp0.x);
                fma2(acc[1 * 4 + q], v[q], wp0.y);
                fma2(acc[2 * 4 + q], v[q], wp1.x);
                fma2(acc[3 * 4 + q], v[q], wp1.y);
                fma2(acc[4 * 4 + q], v[q], wp2.x);
                fma2(acc[5 * 4 + q], v[q], wp2.y);
                fma2(acc[6 * 4 + q], v[q], wp3.x);
                fma2(acc[7 * 4 + q], v[q], wp3.y);
            }
        }
    }

    // epilogue: bias, ELU, optional fused residual 2x upsample (per pixel)
    const int Hh = H / 2, Wh = W / 2;
    float rw00[4], rw01[4], rw10[4], rw11[4];
    int ri00[4], ri01[4], ri10[4], ri11[4];
    if (RES) {
#pragma unroll
        for (int q = 0; q < 4; q++) {
            float sy = hv[q]  * 0.5f - 0.25f;
            float sx = pwv[q] * 0.5f - 0.25f;
            float y0f = floorf(sy), x0f = floorf(sx);
            float wy = sy - y0f, wx = sx - x0f;
            int y0 = (int)y0f, x0 = (int)x0f;
            int yc0 = min(max(y0, 0), Hh - 1), yc1 = min(max(y0 + 1, 0), Hh - 1);
            int xc0 = min(max(x0, 0), Wh - 1), xc1 = min(max(x0 + 1, 0), Wh - 1);
            rw00[q] = (1.0f - wy) * (1.0f - wx);
            rw01[q] = (1.0f - wy) * wx;
            rw10[q] = wy * (1.0f - wx);
            rw11[q] = wy * wx;
            ri00[q] = yc0 * Wh + xc0; ri01[q] = yc0 * Wh + xc1;
            ri10[q] = yc1 * Wh + xc0; ri11[q] = yc1 * Wh + xc1;
        }
    }
    const float* resb = RES ? (res + (size_t)b * 64 * Hh * Wh) : nullptr;

#pragma unroll
    for (int j = 0; j < 8; j++) {
        int o0 = cgrp + 2 * j;
        float b0 = __ldg(bias + o0);
        float b1 = __ldg(bias + o0 + 1);
#pragma unroll
        for (int q = 0; q < 4; q++) {
            float2 f = unpack2(acc[j * 4 + q]);
            float v0 = f.x + b0;
            float v1 = f.y + b1;
            v0 = v0 > 0.0f ? v0 : expm1f(v0);
            v1 = v1 > 0.0f ? v1 : expm1f(v1);
            if (RES) {
                const float* rp0 = resb + (size_t)o0 * Hh * Wh;
                const float* rp1 = rp0 + Hh * Wh;
                float ru = rw00[q] * __ldg(rp0 + ri00[q]) + rw01[q] * __ldg(rp0 + ri01[q])
                         + rw10[q] * __ldg(rp0 + ri10[q]) + rw11[q] * __ldg(rp0 + ri11[q]);
                float rv = rw00[q] * __ldg(rp1 + ri00[q]) + rw01[q] * __ldg(rp1 + ri01[q])
                         + rw10[q] * __ldg(rp1 + ri10[q]) + rw11[q] * __ldg(rp1 + ri11[q]);
                v0 += ru;
                v1 += rv;
            }
            out[(((size_t)b * 64 + o0)     * H + hv[q]) * W + pwv[q]] = v0;
            out[(((size_t)b * 64 + o0 + 1) * H + hv[q]) * W + pwv[q]] = v1;
        }
    }
}

// ---------------------------------------------------------------------------
// kernel_launch
// inputs: x, ow1, ob1, w1, b1, ow2, ob2, w2, b2, rw, rb
// ---------------------------------------------------------------------------
extern "C" void kernel_launch(void* const* d_in, const int* in_sizes, int n_in,
                              void* d_out, int out_size) {
    (void)in_sizes; (void)n_in; (void)out_size;
    const float* x   = (const float*)d_in[0];
    const float* ow1 = (const float*)d_in[1];
    const float* ob1 = (const float*)d_in[2];
    const float* w1  = (const float*)d_in[3];
    const float* b1  = (const float*)d_in[4];
    const float* ow2 = (const float*)d_in[5];
    const float* ob2 = (const float*)d_in[6];
    const float* w2  = (const float*)d_in[7];
    const float* b2  = (const float*)d_in[8];
    const float* rw  = (const float*)d_in[9];
    const float* rb  = (const float*)d_in[10];
    float* out = (float*)d_out;

    float *off1, *h1, *h1up, *off2, *r, *w1t, *w2t, *ow1t, *ow2t, *xt, *h1upt;
    cudaGetSymbolAddress((void**)&off1,  g_off1);
    cudaGetSymbolAddress((void**)&h1,    g_h1);
    cudaGetSymbolAddress((void**)&h1up,  g_h1up);
    cudaGetSymbolAddress((void**)&off2,  g_off2);
    cudaGetSymbolAddress((void**)&r,     g_r);
    cudaGetSymbolAddress((void**)&w1t,   g_w1t);
    cudaGetSymbolAddress((void**)&w2t,   g_w2t);
    cudaGetSymbolAddress((void**)&ow1t,  g_ow1t);
    cudaGetSymbolAddress((void**)&ow2t,  g_ow2t);
    cudaGetSymbolAddress((void**)&xt,    g_xt);
    cudaGetSymbolAddress((void**)&h1upt, g_h1upt);

    // 0: all weight transposes in one launch
    transpose_all_kernel<<<(110592 + 255) / 256, 256>>>(w1, w2, ow1, ow2);

    // 1: x -> NHWC (gather source for dcn1)
    nchw_to_nhwc_kernel<<<dim3(H1_ * W1_ / 64, B_), 256>>>(x, xt, H1_ * W1_);

    // 2: residual path 1x1 conv (independent of stage 1)
    conv1x1_kernel<<<dim3((H1_ * W1_ + 255) / 256, B_), 256>>>(x, rw, rb, r, H1_ * W1_);

    // 3: stage-1 offsets (16x32 tiles, double-buffered)
    conv3x3_27_kernel<<<dim3(W1_ / 16, H1_ / 32, B_), 256>>>(x, ow1t, ob1, off1, H1_, W1_);

    // 4: stage-1 dcn + elu (64x2 tile = 128 px), NHWC gather
    dcn_kernel<H1_, W1_, 64, 2, false><<<dim3(W1_ / 64, H1_ / 2, B_), 128>>>(xt, off1, w1t, b1, nullptr, h1);

    // 5: upsample (NCHW, needed by conv3x3 stage 2)
    upsample2x_kernel<<<(B_ * C_ * H2_ * W2_ + 255) / 256, 256>>>(h1, h1up, B_ * C_, H1_, W1_);

    // 6: h1up -> NHWC (gather source for dcn2)
    nchw_to_nhwc_kernel<<<dim3(H2_ * W2_ / 64, B_), 256>>>(h1up, h1upt, H2_ * W2_);

    // 7: stage-2 offsets (16x32 tiles, double-buffered)
    conv3x3_27_kernel<<<dim3(W2_ / 16, H2_ / 32, B_), 256>>>(h1up, ow2t, ob2, off2, H2_, W2_);

    // 8: stage-2 dcn + elu + fused residual upsample (128x1 tile), NHWC gather
    dcn_kernel<H2_, W2_, 128, 1, true><<<dim3(W2_ / 128, H2_, B_), 128>>>(h1upt, off2, w2t, b2, r, out);
}

// round 12
// speedup vs baseline: 1.3563x; 1.3563x over previous
#include <cuda_runtime.h>
#include <math.h>

// ---------------------------------------------------------------------------
// Problem constants
//   x:  (2, 64, 192, 192)
//   out:(2, 64, 384, 384) fp32
// ---------------------------------------------------------------------------
#define B_   2
#define C_   64
#define H1_  192
#define W1_  192
#define H2_  384
#define W2_  384

// ---------------------------------------------------------------------------
// f32x2 packed-FMA helpers (sm_103a FFMA2 — only reachable via PTX)
// ---------------------------------------------------------------------------
__device__ __forceinline__ unsigned long long pack2(float v) {
    unsigned long long r;
    asm("mov.b64 %0, {%1, %1};" : "=l"(r) : "f"(v));
    return r;
}
__device__ __forceinline__ void fma2(unsigned long long& d,
                                     unsigned long long a,
                                     unsigned long long b) {
    asm("fma.rn.f32x2 %0, %1, %2, %0;" : "+l"(d) : "l"(a), "l"(b));
}
__device__ __forceinline__ float2 unpack2(unsigned long long v) {
    float2 f;
    asm("mov.b64 {%0, %1}, %2;" : "=f"(f.x), "=f"(f.y) : "l"(v));
    return f;
}

// ---------------------------------------------------------------------------
// Scratch (static device globals; no cudaMalloc allowed)
// ---------------------------------------------------------------------------
__device__ float g_off1[B_ * 27 * H1_ * W1_];   // offsets stage 1
__device__ float g_h1  [B_ * C_ * H1_ * W1_];   // elu(dcn1)
__device__ float g_h1up[B_ * C_ * H2_ * W2_];   // upsample2x(h1)
__device__ float g_off2[B_ * 27 * H2_ * W2_];   // offsets stage 2
__device__ float g_r   [B_ * C_ * H1_ * W1_];   // 1x1 residual conv
__device__ float g_w1t [9 * 64 * 64];           // dcn1 weights (k,c,o)
__device__ float g_w2t [9 * 64 * 64];           // dcn2 weights (k,c,o)
__device__ float g_ow1t[64 * 9 * 32];           // offset conv1 weights (c,k,o-pad32)
__device__ float g_ow2t[64 * 9 * 32];           // offset conv2 weights (c,k,o-pad32)

// ---------------------------------------------------------------------------
// Merged weight transposes (one launch)
// ---------------------------------------------------------------------------
__global__ void transpose_all_kernel(const float* __restrict__ w1,
                                     const float* __restrict__ w2,
                                     const float* __restrict__ ow1,
                                     const float* __restrict__ ow2) {
    int i = blockIdx.x * 256 + threadIdx.x;
    if (i < 2 * 36864) {
        const float* w = (i < 36864) ? w1 : w2;
        float* wt = (i < 36864) ? g_w1t : g_w2t;
        int j = (i < 36864) ? i : i - 36864;
        int o = j & 63;
        int c = (j >> 6) & 63;
        int k = j >> 12;
        wt[j] = w[(o * 64 + c) * 9 + k];
    } else {
        int j = i - 2 * 36864;
        if (j >= 2 * 18432) return;
        const float* w = (j < 18432) ? ow1 : ow2;
        float* wt = (j < 18432) ? g_ow1t : g_ow2t;
        int jj = (j < 18432) ? j : j - 18432;
        int c = jj / 288;
        int r = jj - c * 288;
        int k = r >> 5;
        int o = r & 31;
        wt[jj] = (o < 27) ? w[(o * 64 + c) * 9 + k] : 0.0f;
    }
}

// ---------------------------------------------------------------------------
// 3x3 conv, Cin=64, Cout=27 (28 acc = 14 f32x2 per row group), pad=1, NCHW
// Templated tile height TR (16 or 32): block = 256 thr = 16 x TR output tile,
// TR/16 rows per thread. Double-buffered halo+weights, one sync per channel.
// TR=16 for small grids (stage 1: grid 288 -> 2 blocks/SM); TR=32 for stage 2.
// ---------------------------------------------------------------------------
template <int TR>
__global__ void __launch_bounds__(256) conv3x3_27_kernel(
    const float* __restrict__ in,    // (B,64,H,W)
    const float* __restrict__ wt,    // (64,9,32) transposed+padded
    const float* __restrict__ bias,  // (27)
    float* __restrict__ out,         // (B,27,H,W)
    int H, int W)
{
    constexpr int NR = TR + 2;                 // rows incl. halo
    constexpr int CNT = NR * 18;               // halo tile elements
    constexpr int SLOTS = (CNT + 255) / 256;
    constexpr int RG = TR / 16;                // row groups per thread

    __shared__ __align__(16) float tile[2][NR][18];
    __shared__ __align__(16) float wsm[2][288];

    const int tid = threadIdx.x;
    const int tx = tid & 15;
    const int ty = tid >> 4;          // 0..15
    const int bx = blockIdx.x * 16;
    const int by = blockIdx.y * TR;
    const int b  = blockIdx.z;

    // hoisted halo-load coordinates
    int gofs[SLOTS];
    bool gval[SLOTS];
    bool ghave[SLOTS];
#pragma unroll
    for (int s = 0; s < SLOTS; s++) {
        int idx = tid + s * 256;
        ghave[s] = (idx < CNT);
        int iy = idx / 18, ix = idx - iy * 18;
        int yy = by + iy - 1, xx = bx + ix - 1;
        gval[s] = ghave[s] && (yy >= 0 && yy < H && xx >= 0 && xx < W);
        gofs[s] = yy * W + xx;
    }
    const bool haveW1 = (tid < 32);   // weights slot1 = tid+256 < 288

    unsigned long long acc2[RG][14];
#pragma unroll
    for (int rg = 0; rg < RG; rg++)
#pragma unroll
        for (int j = 0; j < 14; j++) acc2[rg][j] = 0ULL;

    const float* pc = in + (size_t)b * 64 * H * W;
    const float* pw = wt;
    const int HW = H * W;

    // stage channel 0 into buffer 0
#pragma unroll
    for (int s = 0; s < SLOTS; s++)
        if (ghave[s])
            ((float*)tile[0])[tid + s * 256] = gval[s] ? __ldg(pc + gofs[s]) : 0.0f;
    wsm[0][tid] = __ldg(pw + tid);
    if (haveW1) wsm[0][tid + 256] = __ldg(pw + tid + 256);
    __syncthreads();

    for (int c = 0; c < 64; c++) {
        const int cur = c & 1;

        // prefetch next channel into registers (LDG only, overlaps compute)
        float nv[SLOTS];
        float nw0 = 0.0f, nw1 = 0.0f;
        if (c < 63) {
            const float* pn = pc + HW;
            const float* pwn = pw + 288;
#pragma unroll
            for (int s = 0; s < SLOTS; s++)
                nv[s] = (ghave[s] && gval[s]) ? __ldg(pn + gofs[s]) : 0.0f;
            nw0 = __ldg(pwn + tid);
            if (haveW1) nw1 = __ldg(pwn + tid + 256);
        }

        // compute on current buffer
#pragma unroll
        for (int k = 0; k < 9; k++) {
            const ulonglong2* wr = (const ulonglong2*)(&wsm[cur][k * 32]);
#pragma unroll
            for (int rg = 0; rg < RG; rg++) {
                float xv = tile[cur][ty + rg * 16 + k / 3][tx + k % 3];
                unsigned long long xv2 = pack2(xv);
#pragma unroll
                for (int g = 0; g < 7; g++) {
                    ulonglong2 wv = wr[g];
                    fma2(acc2[rg][2 * g + 0], xv2, wv.x);
                    fma2(acc2[rg][2 * g + 1], xv2, wv.y);
                }
            }
        }

        // store prefetched channel into alternate buffer
        if (c < 63) {
            const int nxt = cur ^ 1;
#pragma unroll
            for (int s = 0; s < SLOTS; s++)
                if (ghave[s]) ((float*)tile[nxt])[tid + s * 256] = nv[s];
            wsm[nxt][tid] = nw0;
            if (haveW1) wsm[nxt][tid + 256] = nw1;
        }
        __syncthreads();
        pc += HW;
        pw += 288;
    }

    const int gx = bx + tx;
#pragma unroll
    for (int rg = 0; rg < RG; rg++) {
        const int gy = by + ty + rg * 16;
        float fa[28];
#pragma unroll
        for (int j = 0; j < 14; j++) {
            float2 t0 = unpack2(acc2[rg][j]);
            fa[2 * j] = t0.x; fa[2 * j + 1] = t0.y;
        }
#pragma unroll
        for (int o = 0; o < 27; o++)
            out[(((size_t)b * 27 + o) * H + gy) * W + gx] = fa[o] + __ldg(bias + o);
    }
}

// ---------------------------------------------------------------------------
// 1x1 conv, 64->64 (residual path), f32x2
// ---------------------------------------------------------------------------
__global__ void __launch_bounds__(256) conv1x1_kernel(
    const float* __restrict__ in,   // (B,64,HW)
    const float* __restrict__ w,    // (64,64) (o,c)
    const float* __restrict__ bias, // (64)
    float* __restrict__ out,        // (B,64,HW)
    int HW)
{
    __shared__ __align__(16) float ws[64 * 64];  // transposed: ws[c*64+o]
    const int tid = threadIdx.x;
    for (int i = tid; i < 4096; i += 256) {
        int c = i >> 6, o = i & 63;
        ws[i] = __ldg(w + o * 64 + c);
    }
    __syncthreads();

    const int b = blockIdx.y;
    const int p = blockIdx.x * 256 + tid;
    if (p >= HW) return;

    const float* inb = in + (size_t)b * 64 * HW + p;
    unsigned long long acc2[32];
#pragma unroll
    for (int j = 0; j < 32; j++) acc2[j] = 0ULL;

    for (int c = 0; c < 64; c++) {
        float xv = __ldg(inb + (size_t)c * HW);
        unsigned long long vv = pack2(xv);
        const ulonglong2* wr = (const ulonglong2*)(ws + c * 64);
#pragma unroll
        for (int g = 0; g < 16; g++) {
            ulonglong2 t = wr[g];
            fma2(acc2[2 * g + 0], vv, t.x);
            fma2(acc2[2 * g + 1], vv, t.y);
        }
    }
    float* ob = out + (size_t)b * 64 * HW + p;
#pragma unroll
    for (int j = 0; j < 32; j++) {
        float2 f = unpack2(acc2[j]);
        ob[(size_t)(2 * j + 0) * HW] = f.x + __ldg(bias + 2 * j + 0);
        ob[(size_t)(2 * j + 1) * HW] = f.y + __ldg(bias + 2 * j + 1);
    }
}

// ---------------------------------------------------------------------------
// bilinear 2x upsample, jax.image.resize semantics
// ---------------------------------------------------------------------------
__global__ void __launch_bounds__(256) upsample2x_kernel(
    const float* __restrict__ in, float* __restrict__ out, int BC, int H, int W)
{
    const int W2 = 2 * W, H2 = 2 * H;
    int idx = blockIdx.x * 256 + threadIdx.x;
    int total = BC * H2 * W2;
    if (idx >= total) return;
    int x = idx % W2;
    int t = idx / W2;
    int y = t % H2;
    int c = t / H2;
    float sy = y * 0.5f - 0.25f;
    float sx = x * 0.5f - 0.25f;
    float y0f = floorf(sy), x0f = floorf(sx);
    float wy = sy - y0f, wx = sx - x0f;
    int y0 = (int)y0f, x0 = (int)x0f;
    int yc0 = min(max(y0, 0), H - 1), yc1 = min(max(y0 + 1, 0), H - 1);
    int xc0 = min(max(x0, 0), W - 1), xc1 = min(max(x0 + 1, 0), W - 1);
    const float* p = in + (size_t)c * H * W;
    float v = (1.0f - wy) * ((1.0f - wx) * __ldg(p + yc0 * W + xc0) + wx * __ldg(p + yc0 * W + xc1))
            +         wy  * ((1.0f - wx) * __ldg(p + yc1 * W + xc0) + wx * __ldg(p + yc1 * W + xc1));
    out[idx] = v;
}

// ---------------------------------------------------------------------------
// DCNv2 + ELU (+ optional fused residual-upsample add for stage 2)
// Block = 128 threads = 4 warps. Tile = 128 pixels (TILEW cols x ROWS rows).
// Phase 1: warp w gathers channels [16w,16w+16) for its 4 px/thread -> s_s.
// Phase 2: warp w owns outputs [16w,16w+16) x 128 px; weights via LDS128.
// PREF template: offset prefetch across taps (R9-measured: helps the RES
// variant, hurts the non-RES variant via register pressure).
// ---------------------------------------------------------------------------
template <int H, int W, int TILEW, int ROWS, bool RES, bool PREF>
__global__ void __launch_bounds__(128) dcn_kernel(
    const float* __restrict__ img,   // (B,64,H,W)
    const float* __restrict__ off,   // (B,27,H,W)
    const float* __restrict__ wt,    // (9,64,64) (k,c,o)
    const float* __restrict__ bias,  // (64)
    const float* __restrict__ res,   // (B,64,H/2,W/2) or nullptr
    float* __restrict__ out)         // (B,64,H,W)
{
    static_assert(TILEW * ROWS == 128, "tile must be 128 px");
    __shared__ __align__(16) float s_s[64][128];  // [c][px]
    __shared__ __align__(16) float w_s[4096];     // one tap's 64x64 slab

    const int tid  = threadIdx.x;
    const int lane = tid & 31;
    const int warp = tid >> 5;          // 0..3
    const int cgrp = warp * 16;         // phase-1 channel group == phase-2 o group
    const int h0 = blockIdx.y * ROWS;
    const int bx = blockIdx.x * TILEW;
    const int b  = blockIdx.z;
    const int HW = H * W;
    const float* imgb = img + (size_t)b * 64 * HW;
    const float* offb = off + (size_t)b * 27 * HW;

    // this thread's 4 pixels: px = lane + q*32
    int pwv[4], hv[4], pidx[4];
#pragma unroll
    for (int q = 0; q < 4; q++) {
        int px  = lane + q * 32;
        int row = px / TILEW;
        int col = px - row * TILEW;
        pwv[q] = bx + col;
        hv[q]  = h0 + row;
        pidx[q] = hv[q] * W + pwv[q];
    }

    unsigned long long acc[32];   // [o-pair j(8)][px q(4)] -> acc[j*4+q]
#pragma unroll
    for (int i = 0; i < 32; i++) acc[i] = 0ULL;

    float pdy[4], pdx[4], pmz[4];
    if (PREF) {
#pragma unroll
        for (int q = 0; q < 4; q++) {
            pdy[q] = __ldg(offb + 0 * HW + pidx[q]);
            pdx[q] = __ldg(offb + 1 * HW + pidx[q]);
            pmz[q] = __ldg(offb + 18 * HW + pidx[q]);
        }
    }

    for (int k = 0; k < 9; k++) {
        __syncthreads();  // protect s_s / w_s against previous iteration's readers
        // stage this tap's 64x64 weight slab (128 threads x 8 float4)
        {
            const float4* src = (const float4*)(wt + k * 4096);
            float4* dst = (float4*)w_s;
#pragma unroll
            for (int i = tid; i < 1024; i += 128) dst[i] = src[i];
        }

        // tap params for 4 pixels
        float w00[4], w01[4], w10[4], w11[4];
        int i00[4], i01[4], i10[4], i11[4];
#pragma unroll
        for (int q = 0; q < 4; q++) {
            float dy, dx, mz;
            if (PREF) {
                dy = pdy[q]; dx = pdx[q]; mz = pmz[q];
            } else {
                dy = __ldg(offb + (2 * k) * HW + pidx[q]);
                dx = __ldg(offb + (2 * k + 1) * HW + pidx[q]);
                mz = __ldg(offb + (18 + k) * HW + pidx[q]);
            }
            float m  = 1.0f / (1.0f + expf(-mz));

            float yy = (float)(hv[q] - 1 + k / 3) + dy;
            float xx = (float)(pwv[q] - 1 + k % 3) + dx;
            float y0f = floorf(yy), x0f = floorf(xx);
            float wy = yy - y0f, wx = xx - x0f;
            int y0 = (int)y0f, x0 = (int)x0f;
            int y1 = y0 + 1,   x1 = x0 + 1;
            float fy0 = (y0 >= 0 && y0 < H) ? 1.0f : 0.0f;
            float fy1 = (y1 >= 0 && y1 < H) ? 1.0f : 0.0f;
            float fx0 = (x0 >= 0 && x0 < W) ? 1.0f : 0.0f;
            float fx1 = (x1 >= 0 && x1 < W) ? 1.0f : 0.0f;
            w00[q] = (1.0f - wy) * (1.0f - wx) * fy0 * fx0 * m;
            w01[q] = (1.0f - wy) * wx          * fy0 * fx1 * m;
            w10[q] = wy          * (1.0f - wx) * fy1 * fx0 * m;
            w11[q] = wy          * wx          * fy1 * fx1 * m;
            int yc0 = min(max(y0, 0), H - 1), yc1 = min(max(y1, 0), H - 1);
            int xc0 = min(max(x0, 0), W - 1), xc1 = min(max(x1, 0), W - 1);
            i00[q] = yc0 * W + xc0; i01[q] = yc0 * W + xc1;
            i10[q] = yc1 * W + xc0; i11[q] = yc1 * W + xc1;
        }

        // phase 1: this warp's 16 channels x this thread's 4 pixels
        const float* pc = imgb + (size_t)cgrp * HW;
#pragma unroll
        for (int cc = 0; cc < 16; cc++) {
#pragma unroll
            for (int q = 0; q < 4; q++) {
                float s = w00[q] * __ldg(pc + i00[q]) + w01[q] * __ldg(pc + i01[q])
                        + w10[q] * __ldg(pc + i10[q]) + w11[q] * __ldg(pc + i11[q]);
                s_s[cgrp + cc][lane + q * 32] = s;
            }
            pc += HW;
        }
        __syncthreads();

        // prefetch NEXT tap's offsets (latency hides under GEMM below)
        if (PREF && k < 8) {
#pragma unroll
            for (int q = 0; q < 4; q++) {
                pdy[q] = __ldg(offb + (2 * k + 2) * HW + pidx[q]);
                pdx[q] = __ldg(offb + (2 * k + 3) * HW + pidx[q]);
                pmz[q] = __ldg(offb + (19 + k) * HW + pidx[q]);
            }
        }

        // phase 2: warp's 16 outputs x 128 pixels, 32 FFMA2 per c per thread
#pragma unroll 4
        for (int c = 0; c < 64; c++) {
            unsigned long long v[4];
#pragma unroll
            for (int q = 0; q < 4; q++) v[q] = pack2(s_s[c][lane + q * 32]);
            const ulonglong2* wr = (const ulonglong2*)(w_s + c * 64 + cgrp);
            ulonglong2 wp0 = wr[0], wp1 = wr[1], wp2 = wr[2], wp3 = wr[3];
#pragma unroll
            for (int q = 0; q < 4; q++) {
                fma2(acc[0 * 4 + q], v[q], wp0.x);
                fma2(acc[1 * 4 + q], v[q], wp0.y);
                fma2(acc[2 * 4 + q], v[q], wp1.x);
                fma2(acc[3 * 4 + q], v[q], wp1.y);
                fma2(acc[4 * 4 + q], v[q], wp2.x);
                fma2(acc[5 * 4 + q], v[q], wp2.y);
                fma2(acc[6 * 4 + q], v[q], wp3.x);
                fma2(acc[7 * 4 + q], v[q], wp3.y);
            }
        }
    }

    // epilogue: bias, ELU, optional fused residual 2x upsample (per pixel)
    const int Hh = H / 2, Wh = W / 2;
    float rw00[4], rw01[4], rw10[4], rw11[4];
    int ri00[4], ri01[4], ri10[4], ri11[4];
    if (RES) {
#pragma unroll
        for (int q = 0; q < 4; q++) {
            float sy = hv[q]  * 0.5f - 0.25f;
            float sx = pwv[q] * 0.5f - 0.25f;
            float y0f = floorf(sy), x0f = floorf(sx);
            float wy = sy - y0f, wx = sx - x0f;
            int y0 = (int)y0f, x0 = (int)x0f;
            int yc0 = min(max(y0, 0), Hh - 1), yc1 = min(max(y0 + 1, 0), Hh - 1);
            int xc0 = min(max(x0, 0), Wh - 1), xc1 = min(max(x0 + 1, 0), Wh - 1);
            rw00[q] = (1.0f - wy) * (1.0f - wx);
            rw01[q] = (1.0f - wy) * wx;
            rw10[q] = wy * (1.0f - wx);
            rw11[q] = wy * wx;
            ri00[q] = yc0 * Wh + xc0; ri01[q] = yc0 * Wh + xc1;
            ri10[q] = yc1 * Wh + xc0; ri11[q] = yc1 * Wh + xc1;
        }
    }
    const float* resb = RES ? (res + (size_t)b * 64 * Hh * Wh) : nullptr;

#pragma unroll
    for (int j = 0; j < 8; j++) {
        int o0 = cgrp + 2 * j;
        float b0 = __ldg(bias + o0);
        float b1 = __ldg(bias + o0 + 1);
#pragma unroll
        for (int q = 0; q < 4; q++) {
            float2 f = unpack2(acc[j * 4 + q]);
            float v0 = f.x + b0;
            float v1 = f.y + b1;
            v0 = v0 > 0.0f ? v0 : expm1f(v0);
            v1 = v1 > 0.0f ? v1 : expm1f(v1);
            if (RES) {
                const float* rp0 = resb + (size_t)o0 * Hh * Wh;
                const float* rp1 = rp0 + Hh * Wh;
                float ru = rw00[q] * __ldg(rp0 + ri00[q]) + rw01[q] * __ldg(rp0 + ri01[q])
                         + rw10[q] * __ldg(rp0 + ri10[q]) + rw11[q] * __ldg(rp0 + ri11[q]);
                float rv = rw00[q] * __ldg(rp1 + ri00[q]) + rw01[q] * __ldg(rp1 + ri01[q])
                         + rw10[q] * __ldg(rp1 + ri10[q]) + rw11[q] * __ldg(rp1 + ri11[q]);
                v0 += ru;
                v1 += rv;
            }
            out[(((size_t)b * 64 + o0)     * H + hv[q]) * W + pwv[q]] = v0;
            out[(((size_t)b * 64 + o0 + 1) * H + hv[q]) * W + pwv[q]] = v1;
        }
    }
}

// ---------------------------------------------------------------------------
// kernel_launch
// inputs: x, ow1, ob1, w1, b1, ow2, ob2, w2, b2, rw, rb
// ---------------------------------------------------------------------------
extern "C" void kernel_launch(void* const* d_in, const int* in_sizes, int n_in,
                              void* d_out, int out_size) {
    (void)in_sizes; (void)n_in; (void)out_size;
    const float* x   = (const float*)d_in[0];
    const float* ow1 = (const float*)d_in[1];
    const float* ob1 = (const float*)d_in[2];
    const float* w1  = (const float*)d_in[3];
    const float* b1  = (const float*)d_in[4];
    const float* ow2 = (const float*)d_in[5];
    const float* ob2 = (const float*)d_in[6];
    const float* w2  = (const float*)d_in[7];
    const float* b2  = (const float*)d_in[8];
    const float* rw  = (const float*)d_in[9];
    const float* rb  = (const float*)d_in[10];
    float* out = (float*)d_out;

    float *off1, *h1, *h1up, *off2, *r, *w1t, *w2t, *ow1t, *ow2t;
    cudaGetSymbolAddress((void**)&off1, g_off1);
    cudaGetSymbolAddress((void**)&h1,   g_h1);
    cudaGetSymbolAddress((void**)&h1up, g_h1up);
    cudaGetSymbolAddress((void**)&off2, g_off2);
    cudaGetSymbolAddress((void**)&r,    g_r);
    cudaGetSymbolAddress((void**)&w1t,  g_w1t);
    cudaGetSymbolAddress((void**)&w2t,  g_w2t);
    cudaGetSymbolAddress((void**)&ow1t, g_ow1t);
    cudaGetSymbolAddress((void**)&ow2t, g_ow2t);

    // 0: all weight transposes in one launch
    transpose_all_kernel<<<(110592 + 255) / 256, 256>>>(w1, w2, ow1, ow2);

    // 1: residual path 1x1 conv (independent of stage 1)
    conv1x1_kernel<<<dim3((H1_ * W1_ + 255) / 256, B_), 256>>>(x, rw, rb, r, H1_ * W1_);

    // 2: stage-1 offsets — 16x16 tiles (grid 288 = 2 blocks/SM vs 144 before)
    conv3x3_27_kernel<16><<<dim3(W1_ / 16, H1_ / 16, B_), 256>>>(x, ow1t, ob1, off1, H1_, W1_);

    // 3: stage-1 dcn + elu (64x2 tile = 128 px), NO prefetch (R10 measured best)
    dcn_kernel<H1_, W1_, 64, 2, false, false><<<dim3(W1_ / 64, H1_ / 2, B_), 128>>>(x, off1, w1t, b1, nullptr, h1);

    // 4: upsample
    upsample2x_kernel<<<(B_ * C_ * H2_ * W2_ + 255) / 256, 256>>>(h1, h1up, B_ * C_, H1_, W1_);

    // 5: stage-2 offsets — 16x32 tiles (grid 576, measured best)
    conv3x3_27_kernel<32><<<dim3(W2_ / 16, H2_ / 32, B_), 256>>>(h1up, ow2t, ob2, off2, H2_, W2_);

    // 6: stage-2 dcn + elu + fused residual upsample, WITH prefetch (R9 best)
    dcn_kernel<H2_, W2_, 128, 1, true, true><<<dim3(W2_ / 128, H2_, B_), 128>>>(h1up, off2, w2t, b2, r, out);
}